// round 15
// baseline (speedup 1.0000x reference)
#include <cuda_runtime.h>
#include <cuda_fp16.h>
#include <cstdint>

// Problem constants
#define Bq 16
#define Dq 128
#define Lq 4096
#define Kq 8
#define Nq 1024
#define ZQ_ELEMS (Bq*Kq*Dq*Lq)

#define THREADS 256
#define ROWS 64
#define NCH 64
#define NCHUNKS 16             // per stage
#define GTOT (Kq*NCHUNKS)      // 128 global chunks
#define NTILES ((Lq/ROWS)*Bq)  // 1024
#define GRID 296
#define PITCHB 272             // 136 fp16 per row (128 + 8 pad): conflict-free ldmatrix
#define B_TILE 17408           // 64 rows x PITCHB
#define B_CHUNK B_TILE
#define B_CHUNK_F4 (B_CHUNK/16)  // 1088

// Shared memory byte offsets (per-CTA 109840 -> 2 CTAs/SM)
#define SM_A32    0            // fp32 residual 64 x 132 = 33792 (persistent across stages)
#define SM_AH     33792        // fp16 residual tile 17408 (cap dump overlays this between stages)
#define SM_CAP    33792
#define SM_B      51200        // 3-buffer ring: 3 x 17408 = 52224
#define SM_CNORM  103424       // 1024 floats
#define SM_CAND   107520       // int[64][8] = 2048
#define SM_ROWIDX 109568       // int[64]
#define SM_TILE   109824       // int (stolen tile broadcast)
#define SMEM_BYTES 109840

// __device__ scratch (allocation-free rule)
__device__ float g_cnorm[Kq*Nq];
__device__ int   g_tile;
// per global chunk g: 64 rows x 136 fp16, contiguous over g = k*16+c
__device__ __half g_cbh[GTOT*64*136];

// ---------------- PTX helpers (plain sm_80-class) ----------------
__device__ __forceinline__ uint32_t s2u(const void* p) {
    uint32_t a;
    asm("{ .reg .u64 t; cvta.to.shared.u64 t, %1; cvt.u32.u64 %0, t; }" : "=r"(a) : "l"(p));
    return a;
}
#define CP16(d,s)    asm volatile("cp.async.cg.shared.global [%0], [%1], 16;" :: "r"(d), "l"(s) : "memory")
#define CP_COMMIT()  asm volatile("cp.async.commit_group;" ::: "memory")
template<int N> __device__ __forceinline__ void cp_wait() {
    asm volatile("cp.async.wait_group %0;" :: "n"(N) : "memory");
}
__device__ __forceinline__ void ldsm4(uint32_t& r0, uint32_t& r1, uint32_t& r2, uint32_t& r3,
                                      uint32_t addr) {
    asm volatile("ldmatrix.sync.aligned.m8n8.x4.shared.b16 {%0,%1,%2,%3}, [%4];"
                 : "=r"(r0), "=r"(r1), "=r"(r2), "=r"(r3) : "r"(addr));
}
__device__ __forceinline__ void mma16816(float* d, const uint32_t* a, uint32_t b0, uint32_t b1) {
    asm volatile(
        "mma.sync.aligned.m16n8k16.row.col.f32.f16.f16.f32 "
        "{%0,%1,%2,%3}, {%4,%5,%6,%7}, {%8,%9}, {%0,%1,%2,%3};"
        : "+f"(d[0]), "+f"(d[1]), "+f"(d[2]), "+f"(d[3])
        : "r"(a[0]), "r"(a[1]), "r"(a[2]), "r"(a[3]), "r"(b0), "r"(b1));
}
// IEEE float -> order-preserving uint32
__device__ __forceinline__ uint32_t f2key(float f) {
    uint32_t b = __float_as_uint(f);
    return b ^ ((b & 0x80000000u) ? 0xFFFFFFFFu : 0x80000000u);
}

// ---------------- prep kernels ----------------
__global__ void cnorm_kernel(const float* __restrict__ cb) {
    if (blockIdx.x == 0 && threadIdx.x == 0) g_tile = 0;   // reset steal counter
    int gw   = (blockIdx.x * blockDim.x + threadIdx.x) >> 5;
    int lane = threadIdx.x & 31;
    if (gw >= Kq * Nq) return;
    float4 v = *(const float4*)&cb[(size_t)gw * Dq + lane * 4];
    float s = v.x*v.x + v.y*v.y + v.z*v.z + v.w*v.w;
    #pragma unroll
    for (int off = 16; off > 0; off >>= 1)
        s += __shfl_xor_sync(0xffffffffu, s, off);
    if (lane == 0) g_cnorm[gw] = s;
}

// codebook fp32 -> fp16, padded chunked image (64-code chunks, linear in g)
__global__ void prep_kernel(const float* __restrict__ cb) {
    int idx = blockIdx.x * 256 + threadIdx.x;
    if (idx >= Kq * Nq * Dq) return;
    int d = idx & (Dq - 1);
    int n = (idx >> 7) & (Nq - 1);
    int k = idx >> 17;
    size_t o = ((size_t)(k * NCHUNKS + (n >> 6)) * 64 + (n & 63)) * 136 + d;
    g_cbh[o] = __float2half(cb[idx]);
}

// ---------------- fused persistent kernel ----------------
__device__ __forceinline__ void prefetchB(int g, uint32_t dst, int tid) {
    const char* src = (const char*)g_cbh + (size_t)g * B_CHUNK;
    #pragma unroll
    for (int j = 0; j < 5; ++j) {
        int f4 = tid + j * THREADS;
        if (f4 < B_CHUNK_F4) {
            uint32_t o = (uint32_t)f4 * 16u;
            CP16(dst + o, src + o);
        }
    }
}

__global__ void __launch_bounds__(THREADS, 2)
vq_all(const float* __restrict__ x, const float* __restrict__ cb,
       float* __restrict__ out, float* __restrict__ idxOut)
{
    extern __shared__ char smem[];
    const uint32_t sb = s2u(smem);
    const int tid  = threadIdx.x;
    const int wid  = tid >> 5;
    const int lane = tid & 31;
    const int wm   = wid >> 2;          // 0..1 : m half (32 rows)
    const int wn   = wid & 3;           // 0..3 : n quarter (16 cols)
    const int mb   = wm * 32;
    const int nb   = wn * 16;

    float* A32    = (float*)(smem + SM_A32);
    float* cnormS = (float*)(smem + SM_CNORM);
    int*   rowIdx = (int*)  (smem + SM_ROWIDX);
    int*   sTile  = (int*)  (smem + SM_TILE);

    // ldmatrix lane offsets (validated Rounds 6-14)
    const int grp = lane >> 3, win = lane & 7;
    const uint32_t aLaneOff = (uint32_t)((win + (grp & 1) * 8) * PITCHB + ((grp >> 1) * 8) * 2);
    const uint32_t bLaneOff = (uint32_t)((win + (grp >> 1) * 8) * PITCHB + ((grp & 1) * 8) * 2);
    const int r4 = lane >> 2, c2 = (lane & 3) * 2;

    const int lR = tid & 63;
    const int d0 = (tid >> 6) * 32;

    for (;;) {
        if (tid == 0) *sTile = atomicAdd(&g_tile, 1);
        __syncthreads();
        const int t = *sTile;
        if (t >= NTILES) break;
        const int b  = t >> 6;
        const int l0 = (t & 63) * ROWS;

        // initial residual = x : fp32 tile + fp16 tile
        {
            const size_t base = ((size_t)b * Dq) * Lq + l0;
            #pragma unroll
            for (int i = 0; i < 8; ++i) {
                int q  = tid + THREADS * i;       // 2048 float4
                int d  = q >> 4;
                int l4 = q & 15;
                float4 v = *(const float4*)&x[base + (size_t)d * Lq + l4 * 4];
                float vv[4] = {v.x, v.y, v.z, v.w};
                #pragma unroll
                for (int e = 0; e < 4; ++e) {
                    int l = l4 * 4 + e;
                    A32[l * 132 + d] = vv[e];
                    *(__half*)(smem + SM_AH + (uint32_t)(l * PITCHB + d * 2)) = __float2half(vv[e]);
                }
            }
        }

        float cum[32];
        #pragma unroll
        for (int i = 0; i < 32; ++i) cum[i] = 0.0f;

        // ring prologue: chunks 0, 1
        prefetchB(0, sb + SM_B, tid);           CP_COMMIT();
        prefetchB(1, sb + SM_B + B_TILE, tid);  CP_COMMIT();

        for (int k = 0; k < Kq; ++k) {
            for (int i = tid; i < Nq; i += THREADS)
                cnormS[i] = g_cnorm[k * Nq + i];

            uint32_t top4[4][4];
            #pragma unroll
            for (int s = 0; s < 4; ++s)
                #pragma unroll
                for (int i = 0; i < 4; ++i) top4[s][i] = 0xFFFFFFFFu;

            for (int c = 0; c < NCHUNKS; ++c) {
                const int g = k * NCHUNKS + c;
                cp_wait<1>();
                __syncthreads();     // data ready + all warps done with buf[(g-1)%3]
                const uint32_t bufOff = SM_B + (uint32_t)((g % 3) * B_TILE);

                float acc[2][2][4];
                #pragma unroll
                for (int f = 0; f < 2; ++f)
                    #pragma unroll
                    for (int j = 0; j < 2; ++j)
                        #pragma unroll
                        for (int e = 0; e < 4; ++e) acc[f][j][e] = 0.0f;

                const uint32_t aHB = sb + SM_AH + (uint32_t)(mb * PITCHB) + aLaneOff;
                const uint32_t bHB = sb + bufOff + (uint32_t)(nb * PITCHB) + bLaneOff;

                #pragma unroll
                for (int ks = 0; ks < 8; ++ks) {
                    const uint32_t ko = (uint32_t)(ks * 32);
                    uint32_t ah[2][4], bh[4];
                    #pragma unroll
                    for (int f = 0; f < 2; ++f)
                        ldsm4(ah[f][0], ah[f][1], ah[f][2], ah[f][3],
                              aHB + (uint32_t)(f * 16 * PITCHB) + ko);
                    ldsm4(bh[0], bh[1], bh[2], bh[3], bHB + ko);
                    #pragma unroll
                    for (int f = 0; f < 2; ++f) {
                        mma16816(acc[f][0], ah[f], bh[0], bh[1]);
                        mma16816(acc[f][1], ah[f], bh[2], bh[3]);
                    }
                }

                // prefetch chunk g+2 into buf[(g+2)%3] (safe: entry sync passed)
                if (g + 2 < GTOT)
                    prefetchB(g + 2, sb + SM_B + (uint32_t)(((g + 2) % 3) * B_TILE), tid);
                CP_COMMIT();

                // screened distances -> branchless top-4 capture
                #pragma unroll
                for (int j = 0; j < 2; ++j)
                    #pragma unroll
                    for (int e = 0; e < 2; ++e) {
                        const int n = c * NCH + nb + j * 8 + c2 + e;
                        const float cnv = cnormS[n];
                        #pragma unroll
                        for (int f = 0; f < 2; ++f)
                            #pragma unroll
                            for (int hh = 0; hh < 2; ++hh) {
                                float s = fmaf(-2.0f, acc[f][j][hh * 2 + e], cnv);
                                uint32_t key = (f2key(s) & 0xFFFFFC00u) | (uint32_t)n;
                                const int sl = f * 2 + hh;
                                uint32_t m0 = max(top4[sl][0], key);
                                top4[sl][0] = min(top4[sl][0], key);
                                uint32_t m1 = max(top4[sl][1], m0);
                                top4[sl][1] = min(top4[sl][1], m0);
                                uint32_t m2 = max(top4[sl][2], m1);
                                top4[sl][2] = min(top4[sl][2], m1);
                                top4[sl][3] = min(top4[sl][3], m2);
                            }
                    }
            }

            __syncthreads();   // all warps done reading AH (chunk 15) before cap dump

            // dump capture into AH-overlay region: cap[row][tslot][4]
            uint32_t* cap = (uint32_t*)(smem + SM_CAP);
            const int tslot = wn * 4 + (lane & 3);
            #pragma unroll
            for (int s = 0; s < 4; ++s) {
                int row = mb + (s >> 1) * 16 + (s & 1) * 8 + r4;
                *(uint4*)&cap[((size_t)row * 16 + tslot) * 4] =
                    make_uint4(top4[s][0], top4[s][1], top4[s][2], top4[s][3]);
            }
            __syncthreads();

            // per-row top-8 selection
            int* cand = (int*)(smem + SM_CAND);
            if (tid < ROWS) {
                uint32_t best8[8];
                #pragma unroll
                for (int i = 0; i < 8; ++i) best8[i] = 0xFFFFFFFFu;
                const uint32_t* src = cap + (size_t)tid * 64;
                for (int i = 0; i < 64; ++i) {
                    uint32_t v = src[i];
                    if (v < best8[7]) {
                        int p = 7;
                        while (p > 0 && v < best8[p - 1]) { best8[p] = best8[p - 1]; --p; }
                        best8[p] = v;
                    }
                }
                #pragma unroll
                for (int i = 0; i < 8; ++i)
                    cand[tid * 8 + i] = (int)(best8[i] & 1023u);
            }
            __syncthreads();

            // exact fp32 refine: warp w -> rows w*8 .. w*8+7
            {
                const int cidx = lane >> 2;
                const int part = lane & 3;
                for (int rr = 0; rr < 8; ++rr) {
                    int row = wid * 8 + rr;
                    int n = cand[row * 8 + cidx];
                    const float4* cptr = (const float4*)&cb[((size_t)(k * Nq + n)) * Dq + part * 32];
                    const float4* rptr = (const float4*)&A32[row * 132 + part * 32];
                    float dot = 0.0f;
                    #pragma unroll
                    for (int q = 0; q < 8; ++q) {
                        float4 cv = cptr[q], rv = rptr[q];
                        dot = fmaf(rv.x, cv.x, dot);
                        dot = fmaf(rv.y, cv.y, dot);
                        dot = fmaf(rv.z, cv.z, dot);
                        dot = fmaf(rv.w, cv.w, dot);
                    }
                    dot += __shfl_xor_sync(0xffffffffu, dot, 1);
                    dot += __shfl_xor_sync(0xffffffffu, dot, 2);
                    float dist = cnormS[n] - 2.0f * dot;
                    unsigned long long kk = ((uint64_t)f2key(dist) << 32) | (uint32_t)n;
                    #pragma unroll
                    for (int off = 4; off < 32; off <<= 1) {
                        unsigned long long ok = __shfl_xor_sync(0xffffffffu, kk, off);
                        if (ok < kk) kk = ok;
                    }
                    if (lane == 0) {
                        int bn = (int)(kk & 0xFFFFFFFFu);
                        rowIdx[row] = bn;
                        idxOut[((size_t)b * Lq + l0 + row) * Kq + k] = (float)bn;
                    }
                }
            }
            __syncthreads();

            // tail: code read direct from cb (L2-hot); cum/out/residual/AH rebuild
            {
                const int myIdx = rowIdx[lR];
                const float* crow = &cb[((size_t)(k * Nq + myIdx)) * Dq + d0];
                size_t outBase = (((size_t)b * Kq + k) * Dq) * Lq + l0 + lR;
                #pragma unroll
                for (int q4 = 0; q4 < 8; ++q4) {
                    float4 cv = *(const float4*)&crow[q4 * 4];
                    float cc[4] = {cv.x, cv.y, cv.z, cv.w};
                    #pragma unroll
                    for (int e = 0; e < 4; ++e) {
                        int dd = q4 * 4 + e;
                        int d = d0 + dd;
                        cum[dd] += cc[e];
                        out[outBase + (size_t)d * Lq] = cum[dd];
                        float nr = A32[lR * 132 + d] - cc[e];
                        A32[lR * 132 + d] = nr;
                        *(__half*)(smem + SM_AH + (uint32_t)(lR * PITCHB + d * 2)) = __float2half(nr);
                    }
                }
            }
            __syncthreads();   // AH rebuilt before next stage's ldsm
        }

        cp_wait<0>();
        __syncthreads();       // drain ring before next tile reuses buffers
    }
}

extern "C" void kernel_launch(void* const* d_in, const int* in_sizes, int n_in,
                              void* d_out, int out_size)
{
    const float* x  = (const float*)d_in[0];
    const float* cb = (const float*)d_in[1];
    float* out    = (float*)d_out;
    float* idxOut = out + (size_t)ZQ_ELEMS;

    cudaFuncSetAttribute(vq_all, cudaFuncAttributeMaxDynamicSharedMemorySize, SMEM_BYTES);

    cnorm_kernel<<<(Kq * Nq * 32) / 256, 256>>>(cb);
    prep_kernel<<<(Kq * Nq * Dq) / 256, 256>>>(cb);
    vq_all<<<GRID, THREADS, SMEM_BYTES>>>(x, cb, out, idxOut);
}

// round 16
// speedup vs baseline: 1.0809x; 1.0809x over previous
#include <cuda_runtime.h>
#include <cuda_fp16.h>
#include <cstdint>

// Problem constants
#define Bq 16
#define Dq 128
#define Lq 4096
#define Kq 8
#define Nq 1024
#define ZQ_ELEMS (Bq*Kq*Dq*Lq)

#define THREADS 256
#define ROWS 64
#define NCH 64
#define NCHUNKS 16
#define PITCHB 272             // 136 fp16 per row (128 + 8 pad): conflict-free ldmatrix
#define B_TILE 17408           // 64 rows x PITCHB
#define B_CHUNK B_TILE
#define B_CHUNK_F4 (B_CHUNK/16)  // 1088

// Shared memory byte offsets (per-CTA 92416 -> 2 CTAs/SM)
#define SM_A32    0            // fp32 residual 64 x 132 = 33792 (persistent across stages)
#define SM_AH     33792        // fp16 residual tile 17408 (cap dump overlays between stages)
#define SM_CAP    33792
#define SM_B      51200        // 2 bufs x B_CHUNK = 34816
#define SM_CNORM  86016        // 1024 floats
#define SM_CAND   90112        // int[64][8] = 2048
#define SM_ROWIDX 92160        // int[64]
#define SMEM_BYTES 92416

// __device__ scratch (allocation-free rule)
__device__ float g_cnorm[Kq*Nq];
// per (k,chunk): 64 rows x 136 fp16
__device__ __half g_cbh[Kq*NCHUNKS*64*136];

// ---------------- PTX helpers (plain sm_80-class) ----------------
__device__ __forceinline__ uint32_t s2u(const void* p) {
    uint32_t a;
    asm("{ .reg .u64 t; cvta.to.shared.u64 t, %1; cvt.u32.u64 %0, t; }" : "=r"(a) : "l"(p));
    return a;
}
#define CP16(d,s)    asm volatile("cp.async.cg.shared.global [%0], [%1], 16;" :: "r"(d), "l"(s) : "memory")
#define CP_COMMIT()  asm volatile("cp.async.commit_group;" ::: "memory")
template<int N> __device__ __forceinline__ void cp_wait() {
    asm volatile("cp.async.wait_group %0;" :: "n"(N) : "memory");
}
__device__ __forceinline__ void ldsm4(uint32_t& r0, uint32_t& r1, uint32_t& r2, uint32_t& r3,
                                      uint32_t addr) {
    asm volatile("ldmatrix.sync.aligned.m8n8.x4.shared.b16 {%0,%1,%2,%3}, [%4];"
                 : "=r"(r0), "=r"(r1), "=r"(r2), "=r"(r3) : "r"(addr));
}
__device__ __forceinline__ void mma16816(float* d, const uint32_t* a, uint32_t b0, uint32_t b1) {
    asm volatile(
        "mma.sync.aligned.m16n8k16.row.col.f32.f16.f16.f32 "
        "{%0,%1,%2,%3}, {%4,%5,%6,%7}, {%8,%9}, {%0,%1,%2,%3};"
        : "+f"(d[0]), "+f"(d[1]), "+f"(d[2]), "+f"(d[3])
        : "r"(a[0]), "r"(a[1]), "r"(a[2]), "r"(a[3]), "r"(b0), "r"(b1));
}
// IEEE float -> order-preserving uint32
__device__ __forceinline__ uint32_t f2key(float f) {
    uint32_t b = __float_as_uint(f);
    return b ^ ((b & 0x80000000u) ? 0xFFFFFFFFu : 0x80000000u);
}

// ---------------- prep kernels ----------------
__global__ void cnorm_kernel(const float* __restrict__ cb) {
    int gw   = (blockIdx.x * blockDim.x + threadIdx.x) >> 5;
    int lane = threadIdx.x & 31;
    if (gw >= Kq * Nq) return;
    float4 v = *(const float4*)&cb[(size_t)gw * Dq + lane * 4];
    float s = v.x*v.x + v.y*v.y + v.z*v.z + v.w*v.w;
    #pragma unroll
    for (int off = 16; off > 0; off >>= 1)
        s += __shfl_xor_sync(0xffffffffu, s, off);
    if (lane == 0) g_cnorm[gw] = s;
}

// codebook fp32 -> fp16, padded chunked image (chunks of 64 codes)
__global__ void prep_kernel(const float* __restrict__ cb) {
    int idx = blockIdx.x * 256 + threadIdx.x;
    if (idx >= Kq * Nq * Dq) return;
    int d = idx & (Dq - 1);
    int n = (idx >> 7) & (Nq - 1);
    int k = idx >> 17;
    size_t o = ((size_t)(k * NCHUNKS + (n >> 6)) * 64 + (n & 63)) * 136 + d;
    g_cbh[o] = __float2half(cb[idx]);
}

// ---------------- fused kernel: all 8 stages ----------------
__device__ __forceinline__ void prefetchB(int k, int c, uint32_t dst, int tid) {
    const char* src = (const char*)g_cbh + (size_t)(k * NCHUNKS + c) * B_CHUNK;
    #pragma unroll
    for (int j = 0; j < 5; ++j) {
        int f4 = tid + j * THREADS;
        if (f4 < B_CHUNK_F4) {
            uint32_t o = (uint32_t)f4 * 16u;
            CP16(dst + o, src + o);
        }
    }
}

__global__ void __launch_bounds__(THREADS, 2)
vq_all(const float* __restrict__ x, const float* __restrict__ cb,
       float* __restrict__ out, float* __restrict__ idxOut)
{
    extern __shared__ char smem[];
    const uint32_t sb = s2u(smem);
    const int tid  = threadIdx.x;
    const int wid  = tid >> 5;
    const int lane = tid & 31;
    const int b    = blockIdx.y;
    const int l0   = blockIdx.x * ROWS;
    const int wm   = wid >> 2;          // 0..1 : m half (32 rows)
    const int wn   = wid & 3;           // 0..3 : n quarter (16 cols)
    const int mb   = wm * 32;
    const int nb   = wn * 16;

    float* A32    = (float*)(smem + SM_A32);
    float* cnormS = (float*)(smem + SM_CNORM);
    int*   rowIdx = (int*)  (smem + SM_ROWIDX);

    // initial residual = x : fp32 tile + fp16 tile
    {
        const size_t base = ((size_t)b * Dq) * Lq + l0;
        #pragma unroll
        for (int i = 0; i < 8; ++i) {
            int q  = tid + THREADS * i;       // 2048 float4
            int d  = q >> 4;
            int l4 = q & 15;
            float4 v = *(const float4*)&x[base + (size_t)d * Lq + l4 * 4];
            float vv[4] = {v.x, v.y, v.z, v.w};
            #pragma unroll
            for (int e = 0; e < 4; ++e) {
                int l = l4 * 4 + e;
                A32[l * 132 + d] = vv[e];
                *(__half*)(smem + SM_AH + (uint32_t)(l * PITCHB + d * 2)) = __float2half(vv[e]);
            }
        }
    }
    __syncthreads();   // AH visible before stage-0 A-frag preload

    // ldmatrix lane offsets (validated Rounds 6-15)
    const int grp = lane >> 3, win = lane & 7;
    const uint32_t aLaneOff = (uint32_t)((win + (grp & 1) * 8) * PITCHB + ((grp >> 1) * 8) * 2);
    const uint32_t bLaneOff = (uint32_t)((win + (grp >> 1) * 8) * PITCHB + ((grp & 1) * 8) * 2);
    const int r4 = lane >> 2, c2 = (lane & 3) * 2;

    const uint32_t aHB = sb + SM_AH + (uint32_t)(mb * PITCHB) + aLaneOff;

    const int lR = tid & 63;
    const int d0 = (tid >> 6) * 32;

    for (int k = 0; k < Kq; ++k) {
        for (int i = tid; i < Nq; i += THREADS)
            cnormS[i] = g_cnorm[k * Nq + i];

        // A-fragment preload for ks=0..3 (invariant across all 16 chunks)
        uint32_t afr[4][2][4];
        #pragma unroll
        for (int ks = 0; ks < 4; ++ks)
            #pragma unroll
            for (int f = 0; f < 2; ++f)
                ldsm4(afr[ks][f][0], afr[ks][f][1], afr[ks][f][2], afr[ks][f][3],
                      aHB + (uint32_t)(f * 16 * PITCHB + ks * 32));

        // prefetch B chunks 0, 1
        prefetchB(k, 0, sb + SM_B, tid);           CP_COMMIT();
        prefetchB(k, 1, sb + SM_B + B_CHUNK, tid); CP_COMMIT();

        uint32_t top4[4][4];
        #pragma unroll
        for (int s = 0; s < 4; ++s)
            #pragma unroll
            for (int i = 0; i < 4; ++i) top4[s][i] = 0xFFFFFFFFu;

        for (int c = 0; c < NCHUNKS; ++c) {
            cp_wait<1>();
            __syncthreads();
            const uint32_t bufOff = SM_B + (uint32_t)((c & 1) ? B_CHUNK : 0);

            float acc[2][2][4];
            #pragma unroll
            for (int f = 0; f < 2; ++f)
                #pragma unroll
                for (int j = 0; j < 2; ++j)
                    #pragma unroll
                    for (int e = 0; e < 4; ++e) acc[f][j][e] = 0.0f;

            const uint32_t bHB = sb + bufOff + (uint32_t)(nb * PITCHB) + bLaneOff;

            // ks 0..3: A from registers
            #pragma unroll
            for (int ks = 0; ks < 4; ++ks) {
                uint32_t bh[4];
                ldsm4(bh[0], bh[1], bh[2], bh[3], bHB + (uint32_t)(ks * 32));
                mma16816(acc[0][0], afr[ks][0], bh[0], bh[1]);
                mma16816(acc[0][1], afr[ks][0], bh[2], bh[3]);
                mma16816(acc[1][0], afr[ks][1], bh[0], bh[1]);
                mma16816(acc[1][1], afr[ks][1], bh[2], bh[3]);
            }
            // ks 4..7: A via ldsm
            #pragma unroll
            for (int ks = 4; ks < 8; ++ks) {
                const uint32_t ko = (uint32_t)(ks * 32);
                uint32_t bh[4], a0[4], a1[4];
                ldsm4(bh[0], bh[1], bh[2], bh[3], bHB + ko);
                ldsm4(a0[0], a0[1], a0[2], a0[3], aHB + ko);
                ldsm4(a1[0], a1[1], a1[2], a1[3], aHB + (uint32_t)(16 * PITCHB) + ko);
                mma16816(acc[0][0], a0, bh[0], bh[1]);
                mma16816(acc[0][1], a0, bh[2], bh[3]);
                mma16816(acc[1][0], a1, bh[0], bh[1]);
                mma16816(acc[1][1], a1, bh[2], bh[3]);
            }

            __syncthreads();   // all warps done reading buf before overwrite
            if (c + 2 < NCHUNKS)
                prefetchB(k, c + 2, sb + SM_B + (uint32_t)((c & 1) ? B_CHUNK : 0), tid);
            CP_COMMIT();

            // screened distances -> branchless top-4 capture (overlaps cp.async)
            #pragma unroll
            for (int j = 0; j < 2; ++j)
                #pragma unroll
                for (int e = 0; e < 2; ++e) {
                    const int n = c * NCH + nb + j * 8 + c2 + e;
                    const float cnv = cnormS[n];
                    #pragma unroll
                    for (int f = 0; f < 2; ++f)
                        #pragma unroll
                        for (int hh = 0; hh < 2; ++hh) {
                            float s = fmaf(-2.0f, acc[f][j][hh * 2 + e], cnv);
                            uint32_t key = (f2key(s) & 0xFFFFFC00u) | (uint32_t)n;
                            const int sl = f * 2 + hh;
                            uint32_t m0 = max(top4[sl][0], key);
                            top4[sl][0] = min(top4[sl][0], key);
                            uint32_t m1 = max(top4[sl][1], m0);
                            top4[sl][1] = min(top4[sl][1], m0);
                            uint32_t m2 = max(top4[sl][2], m1);
                            top4[sl][2] = min(top4[sl][2], m1);
                            top4[sl][3] = min(top4[sl][3], m2);
                        }
                }
        }

        cp_wait<0>();
        __syncthreads();   // mainloop done; AH free for cap overlay

        // dump capture into AH-overlay region: cap[row][tslot][4]
        uint32_t* cap = (uint32_t*)(smem + SM_CAP);
        const int tslot = wn * 4 + (lane & 3);
        #pragma unroll
        for (int s = 0; s < 4; ++s) {
            int row = mb + (s >> 1) * 16 + (s & 1) * 8 + r4;
            *(uint4*)&cap[((size_t)row * 16 + tslot) * 4] =
                make_uint4(top4[s][0], top4[s][1], top4[s][2], top4[s][3]);
        }
        __syncthreads();

        // per-row top-8 selection
        int* cand = (int*)(smem + SM_CAND);
        if (tid < ROWS) {
            uint32_t best8[8];
            #pragma unroll
            for (int i = 0; i < 8; ++i) best8[i] = 0xFFFFFFFFu;
            const uint32_t* src = cap + (size_t)tid * 64;
            for (int i = 0; i < 64; ++i) {
                uint32_t v = src[i];
                if (v < best8[7]) {
                    int p = 7;
                    while (p > 0 && v < best8[p - 1]) { best8[p] = best8[p - 1]; --p; }
                    best8[p] = v;
                }
            }
            #pragma unroll
            for (int i = 0; i < 8; ++i)
                cand[tid * 8 + i] = (int)(best8[i] & 1023u);
        }
        __syncthreads();

        // exact fp32 refine: warp w -> rows w*8 .. w*8+7
        {
            const int cidx = lane >> 2;
            const int part = lane & 3;
            for (int rr = 0; rr < 8; ++rr) {
                int row = wid * 8 + rr;
                int n = cand[row * 8 + cidx];
                const float4* cptr = (const float4*)&cb[((size_t)(k * Nq + n)) * Dq + part * 32];
                const float4* rptr = (const float4*)&A32[row * 132 + part * 32];
                float dot = 0.0f;
                #pragma unroll
                for (int q = 0; q < 8; ++q) {
                    float4 cv = cptr[q], rv = rptr[q];
                    dot = fmaf(rv.x, cv.x, dot);
                    dot = fmaf(rv.y, cv.y, dot);
                    dot = fmaf(rv.z, cv.z, dot);
                    dot = fmaf(rv.w, cv.w, dot);
                }
                dot += __shfl_xor_sync(0xffffffffu, dot, 1);
                dot += __shfl_xor_sync(0xffffffffu, dot, 2);
                float dist = cnormS[n] - 2.0f * dot;
                unsigned long long kk = ((uint64_t)f2key(dist) << 32) | (uint32_t)n;
                #pragma unroll
                for (int off = 4; off < 32; off <<= 1) {
                    unsigned long long ok = __shfl_xor_sync(0xffffffffu, kk, off);
                    if (ok < kk) kk = ok;
                }
                if (lane == 0) {
                    int bn = (int)(kk & 0xFFFFFFFFu);
                    rowIdx[row] = bn;
                    idxOut[((size_t)b * Lq + l0 + row) * Kq + k] = (float)bn;
                }
            }
        }
        __syncthreads();

        // tail: code direct from cb (L2-hot); prev-out read; residual + AH rebuild
        {
            const int myIdx = rowIdx[lR];
            const float* crow = &cb[((size_t)(k * Nq + myIdx)) * Dq + d0];
            size_t outBase  = (((size_t)b * Kq + k) * Dq) * Lq + l0 + lR;
            size_t prevBase = outBase - (size_t)Dq * Lq;
            #pragma unroll
            for (int q4 = 0; q4 < 8; ++q4) {
                float4 cv = *(const float4*)&crow[q4 * 4];
                float cc[4] = {cv.x, cv.y, cv.z, cv.w};
                #pragma unroll
                for (int e = 0; e < 4; ++e) {
                    int dd = q4 * 4 + e;
                    int d = d0 + dd;
                    float prev = (k > 0) ? out[prevBase + (size_t)d * Lq] : 0.0f;
                    out[outBase + (size_t)d * Lq] = prev + cc[e];
                    float nr = A32[lR * 132 + d] - cc[e];
                    A32[lR * 132 + d] = nr;
                    *(__half*)(smem + SM_AH + (uint32_t)(lR * PITCHB + d * 2)) = __float2half(nr);
                }
            }
        }
        __syncthreads();   // AH rebuilt before next stage's preload/ldsm
    }
}

extern "C" void kernel_launch(void* const* d_in, const int* in_sizes, int n_in,
                              void* d_out, int out_size)
{
    const float* x  = (const float*)d_in[0];
    const float* cb = (const float*)d_in[1];
    float* out    = (float*)d_out;
    float* idxOut = out + (size_t)ZQ_ELEMS;

    cudaFuncSetAttribute(vq_all, cudaFuncAttributeMaxDynamicSharedMemorySize, SMEM_BYTES);

    cnorm_kernel<<<(Kq * Nq * 32) / 256, 256>>>(cb);
    prep_kernel<<<(Kq * Nq * Dq) / 256, 256>>>(cb);
    vq_all<<<dim3(Lq / ROWS, Bq), THREADS, SMEM_BYTES>>>(x, cb, out, idxOut);
}